// round 11
// baseline (speedup 1.0000x reference)
#include <cuda_runtime.h>
#include <math.h>

#define FULL_MASK 0xffffffffu
#define TWO_PI_F 6.28318530717958647692f

// ---------------- packed f32x2 primitives ----------------
typedef unsigned long long f2;   // two packed fp32 lanes: {lo, hi}

__device__ __forceinline__ f2 f2pack(float a, float b) {
    f2 r; asm("mov.b64 %0, {%1, %2};" : "=l"(r) : "f"(a), "f"(b)); return r;
}
__device__ __forceinline__ void f2unpack(f2 v, float& a, float& b) {
    asm("mov.b64 {%0, %1}, %2;" : "=f"(a), "=f"(b) : "l"(v));
}
__device__ __forceinline__ f2 f2add(f2 a, f2 b) {
    f2 r; asm("add.rn.f32x2 %0, %1, %2;" : "=l"(r) : "l"(a), "l"(b)); return r;
}
__device__ __forceinline__ f2 f2mul(f2 a, f2 b) {
    f2 r; asm("mul.rn.f32x2 %0, %1, %2;" : "=l"(r) : "l"(a), "l"(b)); return r;
}
__device__ __forceinline__ f2 f2fma(f2 a, f2 b, f2 c) {
    f2 r; asm("fma.rn.f32x2 %0, %1, %2, %3;" : "=l"(r) : "l"(a), "l"(b), "l"(c)); return r;
}
__device__ __forceinline__ f2 f2splat(float s) { return f2pack(s, s); }

__device__ __forceinline__ f2 f2shfl_xor(f2 v, int m) {
    float a, b; f2unpack(v, a, b);
    a = __shfl_xor_sync(FULL_MASK, a, m);
    b = __shfl_xor_sync(FULL_MASK, b, m);
    return f2pack(a, b);
}

// digit-swap permutation for radix-4 FFT16: p = 4s+q  ->  k = 4q+s
__device__ __forceinline__ constexpr int dig4c(int p) {
    return ((p & 3) << 2) | (p >> 2);
}

// four-step twiddle table: g_tw512[p*32+lane] = w512^{lane * dig4(p)}
__device__ float2 g_tw512[16 * 32];

__global__ void init_tw_kernel() {
    int e = threadIdx.x;            // 0..511
    int p  = e >> 5;
    int ln = e & 31;
    int k1 = dig4c(p);
    float ang = -(TWO_PI_F / 512.f) * (float)(ln * k1);
    float s, c;
    sincosf(ang, &s, &c);
    g_tw512[p * 32 + ln] = make_float2(c, s);
}

// complex multiply helper: (xr,xi) *= (wr,wi), compile-time w; 5 packed ops
#define CMUL_CONST(XR, XI, WR, WI, NEG) do {                         \
    f2 _wr = f2splat(WR), _wi = f2splat(WI);                         \
    f2 _t1 = f2mul(XI, _wi);                                         \
    f2 _ni = f2fma(XI, _wr, f2mul(XR, _wi));                         \
    XR = f2fma(_t1, NEG, f2mul(XR, _wr));                            \
    XI = _ni;                                                        \
} while (0)

// Per-thread radix-4 16-point DIF FFT over 16 register slots (packed: 2 FFTs).
// Input slot s = time index n. Output slot p holds bin dig4(p) = 4(p&3)+(p>>2).
__device__ __forceinline__ void fft16_r4(f2 (&xr)[16], f2 (&xi)[16], f2 NEG)
{
    const float C1 = 0.9238795325f, C2 = 0.7071067812f, C3 = 0.3826834324f;

    // ---- stage 1: radix-4 over stride-4 groups n=0..3, with w16^{n*s} twiddles
    #pragma unroll
    for (int n = 0; n < 4; ++n) {
        f2 t0r = f2add(xr[n],     xr[n + 8]), t0i = f2add(xi[n],     xi[n + 8]);
        f2 t1r = f2fma(xr[n + 8], NEG, xr[n]), t1i = f2fma(xi[n + 8], NEG, xi[n]);
        f2 t2r = f2add(xr[n + 4], xr[n + 12]), t2i = f2add(xi[n + 4], xi[n + 12]);
        f2 t3r = f2fma(xr[n + 12], NEG, xr[n + 4]), t3i = f2fma(xi[n + 12], NEG, xi[n + 4]);

        xr[n] = f2add(t0r, t2r);
        xi[n] = f2add(t0i, t2i);
        f2 u1r = f2add(t1r, t3i);
        f2 u1i = f2fma(t3r, NEG, t1i);
        f2 u2r = f2fma(t2r, NEG, t0r);
        f2 u2i = f2fma(t2i, NEG, t0i);
        f2 u3r = f2fma(t3i, NEG, t1r);
        f2 u3i = f2add(t1i, t3r);

        if (n == 1) {
            CMUL_CONST(u1r, u1i,  C1, -C3, NEG);   // w16^1
            CMUL_CONST(u2r, u2i,  C2, -C2, NEG);   // w16^2
            CMUL_CONST(u3r, u3i,  C3, -C1, NEG);   // w16^3
        } else if (n == 2) {
            CMUL_CONST(u1r, u1i,  C2, -C2, NEG);   // w16^2
            { f2 tr = u2r; u2r = u2i; u2i = f2mul(tr, NEG); }   // w16^4 = -i
            CMUL_CONST(u3r, u3i, -C2, -C2, NEG);   // w16^6
        } else if (n == 3) {
            CMUL_CONST(u1r, u1i,  C3, -C1, NEG);   // w16^3
            CMUL_CONST(u2r, u2i, -C2, -C2, NEG);   // w16^6
            CMUL_CONST(u3r, u3i, -C1,  C3, NEG);   // w16^9
        }
        xr[n + 4] = u1r;  xi[n + 4] = u1i;
        xr[n + 8] = u2r;  xi[n + 8] = u2i;
        xr[n + 12] = u3r; xi[n + 12] = u3i;
    }

    // ---- stage 2: radix-4 within each 4-slot block (no twiddles)
    #pragma unroll
    for (int s = 0; s < 4; ++s) {
        int b = 4 * s;
        f2 t0r = f2add(xr[b],     xr[b + 2]), t0i = f2add(xi[b],     xi[b + 2]);
        f2 t1r = f2fma(xr[b + 2], NEG, xr[b]), t1i = f2fma(xi[b + 2], NEG, xi[b]);
        f2 t2r = f2add(xr[b + 1], xr[b + 3]), t2i = f2add(xi[b + 1], xi[b + 3]);
        f2 t3r = f2fma(xr[b + 3], NEG, xr[b + 1]), t3i = f2fma(xi[b + 3], NEG, xi[b + 1]);

        xr[b]     = f2add(t0r, t2r);              xi[b]     = f2add(t0i, t2i);
        xr[b + 1] = f2add(t1r, t3i);              xi[b + 1] = f2fma(t3r, NEG, t1i);
        xr[b + 2] = f2fma(t2r, NEG, t0r);         xi[b + 2] = f2fma(t2i, NEG, t0i);
        xr[b + 3] = f2fma(t3i, NEG, t1r);         xi[b + 3] = f2add(t1i, t3r);
    }
}

// Full 512-point packed FFT (two independent FFTs in f2 lanes).
// Output: slot p on lane (=16*par+k1) holds NATURAL bin k = lane + 32*dig4(p).
// Single-round float4 slab transpose; n3 radix-2 and w32^{n2} odd twiddle fused.
__device__ __forceinline__ void fft512D(f2 (&xr)[16], f2 (&xi)[16],
                                        int lane, int par,
                                        ulonglong2* __restrict__ slab,
                                        f2 NEG, f2 SP)
{
    constexpr float W32R_[16] = {
        1.f, 0.98078528f, 0.92387953f, 0.83146961f, 0.70710678f, 0.55557023f,
        0.38268343f, 0.19509032f, 0.f, -0.19509032f, -0.38268343f, -0.55557023f,
        -0.70710678f, -0.83146961f, -0.92387953f, -0.98078528f };
    constexpr float W32I_[16] = {
        0.f, -0.19509032f, -0.38268343f, -0.55557023f, -0.70710678f, -0.83146961f,
        -0.92387953f, -0.98078528f, -1.f, -0.98078528f, -0.92387953f, -0.83146961f,
        -0.70710678f, -0.55557023f, -0.38268343f, -0.19509032f };

    fft16_r4(xr, xi, NEG);

    #pragma unroll
    for (int p = 1; p < 16; ++p) {
        float2 w = __ldg(&g_tw512[p * 32 + lane]);
        f2 wr = f2splat(w.x), wi = f2splat(w.y);
        f2 t1 = f2mul(xi[p], wi);
        f2 ni = f2fma(xi[p], wr, f2mul(xr[p], wi));
        xr[p] = f2fma(t1, NEG, f2mul(xr[p], wr));
        xi[p] = ni;
    }

    const int wb = (lane & 15) * 33;

    __syncwarp();
    #pragma unroll
    for (int p = 0; p < 16; ++p)
        slab[dig4c(p) * 33 + lane] = make_ulonglong2(xr[p], xi[p]);
    __syncwarp();
    #pragma unroll
    for (int s = 0; s < 16; ++s) {
        ulonglong2 y0 = slab[wb + s];
        ulonglong2 y1 = slab[wb + s + 16];
        f2 dr = f2fma((f2)y1.x, SP, (f2)y0.x);
        f2 di = f2fma((f2)y1.y, SP, (f2)y0.y);
        if (s == 0) {
            xr[0] = dr; xi[0] = di;
        } else {
            float cr  = par ? W32R_[s] : 1.f;
            float ci  = par ? W32I_[s] : 0.f;
            float cin = par ? -W32I_[s] : 0.f;
            f2 wr = f2splat(cr), wi = f2splat(ci), win = f2splat(cin);
            xr[s] = f2fma(di, win, f2mul(dr, wr));
            xi[s] = f2fma(di, wr,  f2mul(dr, wi));
        }
    }

    fft16_r4(xr, xi, NEG);
}

// Quad scheme: per 4 rows (a,b,c,d) process 3 packed FFTs instead of 4:
//   T:  FFT(t_a + i t_b | t_c + i t_d)   -> spectrum to smem (packed, natural k)
//   Z0: FFT(h_a + i r_a | h_b + i r_b)   -> reduce with pair-(a,b) spectrum
//   Z1: FFT(h_c + i r_c | h_d + i r_d)   -> reduce with pair-(c,d) spectrum
// Recovery (conj symmetry of real t):
//   even row: out = Im( sum Z^2 c0 ) / (4D),  c0 = conj(Tc[k]) + Tc[-k]
//   odd  row: out = Re( sum Z^2 c1 ) / (4D),  c1 = conj(Tc[k]) - Tc[-k]
__global__ void __launch_bounds__(128, 4)
hole_kernel(const float* __restrict__ h, const float* __restrict__ r,
            const float* __restrict__ t, float* __restrict__ out, int nrows)
{
    const int lane = threadIdx.x & 31;
    const int wid  = threadIdx.x >> 5;
    const int warp = blockIdx.x * 4 + wid;
    const int nw   = gridDim.x * 4;
    const int par  = lane >> 4;

    __shared__ ulonglong2 slab_s[4][16 * 33];   // 8.25 KB/warp transpose slab
    __shared__ f2 tc_r[4][512];                 // 4 KB/warp: Re Tc (pair ab | cd)
    __shared__ f2 tc_i[4][512];                 // 4 KB/warp: Im Tc
    ulonglong2* __restrict__ slab = slab_s[wid];
    f2* __restrict__ tcr_w = tc_r[wid];
    f2* __restrict__ tci_w = tc_i[wid];

    const f2 NEG = f2splat(-1.f);
    const f2 SP  = f2splat(par ? -1.f : 1.f);

    for (int base = warp; base < nrows; base += 4 * nw) {
        int rw[4];
        #pragma unroll
        for (int j = 0; j < 4; ++j) {
            int rj = base + j * nw;
            rw[j] = (rj < nrows) ? rj : base;
        }

        // ===== T phase: packed FFT(t_a + i t_b | t_c + i t_d) =====
        {
            const float* ta = t + (size_t)rw[0] * 512 + lane;
            const float* tb = t + (size_t)rw[1] * 512 + lane;
            const float* tc = t + (size_t)rw[2] * 512 + lane;
            const float* td = t + (size_t)rw[3] * 512 + lane;
            f2 xr[16], xi[16];
            #pragma unroll
            for (int s = 0; s < 16; ++s) {
                xr[s] = f2pack(ta[32 * s], tc[32 * s]);
                xi[s] = f2pack(tb[32 * s], td[32 * s]);
            }
            fft512D(xr, xi, lane, par, slab, NEG, SP);

            // packed spectrum store by natural k (WAR-safe: all lanes passed the
            // slab syncwarps inside fft512D after the previous quad's reads)
            __syncwarp();
            #pragma unroll
            for (int p = 0; p < 16; ++p) {
                int k = lane + 32 * dig4c(p);
                tcr_w[k] = xr[p];
                tci_w[k] = xi[p];
            }
            __syncwarp();
        }

        // ===== Z phases (zp compile-time): zp=0 rows (a,b); zp=1 rows (c,d) =====
        #pragma unroll
        for (int zp = 0; zp < 2; ++zp) {
            int r0 = rw[2 * zp], r1 = rw[2 * zp + 1];
            const float* h0 = h + (size_t)r0 * 512 + lane;
            const float* h1 = h + (size_t)r1 * 512 + lane;
            const float* rr0 = r + (size_t)r0 * 512 + lane;
            const float* rr1 = r + (size_t)r1 * 512 + lane;

            f2 xr[16], xi[16];
            #pragma unroll
            for (int s = 0; s < 16; ++s) {
                xr[s] = f2pack(h0[32 * s], h1[32 * s]);
                xi[s] = f2pack(rr0[32 * s], rr1[32 * s]);
            }
            fft512D(xr, xi, lane, par, slab, NEG, SP);   // (Z0[k] | Z1[k])

            // lo accumulates Im(Z0^2 c0); hi accumulates Re(Z1^2 c1)
            f2 acc = f2splat(0.f);
            #pragma unroll
            for (int p = 0; p < 16; ++p) {
                int ka = lane + 32 * dig4c(p);
                int km = (512 - ka) & 511;

                float tcr, tci, tmr, tmi;
                {   // select this phase's pair (zp is compile-time)
                    float lo, hi;
                    f2unpack(tcr_w[ka], lo, hi); tcr = zp ? hi : lo;
                    f2unpack(tci_w[ka], lo, hi); tci = zp ? hi : lo;
                    f2unpack(tcr_w[km], lo, hi); tmr = zp ? hi : lo;
                    f2unpack(tci_w[km], lo, hi); tmi = zp ? hi : lo;
                }

                float c0i = tmi - tci;     // Im c0
                float c0r = tcr + tmr;     // Re c0
                float c1r = tcr - tmr;     // Re c1
                float nc1i = tci + tmi;    // -Im c1
                f2 X = f2pack(c0i, c1r);
                f2 Y = f2pack(c0r, nc1i);

                f2 a2 = f2mul(xr[p], xr[p]);
                f2 b2 = f2mul(xi[p], xi[p]);
                f2 Wr = f2fma(b2, NEG, a2);        // Re Z^2
                f2 Wi = f2mul(xr[p], xi[p]);       // (1/2) Im Z^2

                acc = f2fma(Wr, X, acc);           // + ReZ2*c0i | + ReZ2*c1r
                Y = f2add(Y, Y);
                acc = f2fma(Wi, Y, acc);           // + ImZ2*c0r | - ImZ2*c1i
            }

            #pragma unroll
            for (int o = 16; o; o >>= 1)
                acc = f2add(acc, f2shfl_xor(acc, o));

            if (lane == 0) {
                float oa, ob;
                f2unpack(acc, oa, ob);
                int j0 = 2 * zp, j1 = 2 * zp + 1;
                if (base + j0 * nw < nrows) out[base + j0 * nw] = oa * (1.f / 2048.f);
                if (base + j1 * nw < nrows) out[base + j1 * nw] = ob * (1.f / 2048.f);
            }
        }
    }
}

extern "C" void kernel_launch(void* const* d_in, const int* in_sizes, int n_in,
                              void* d_out, int out_size)
{
    const float* h = (const float*)d_in[0];
    const float* r = (const float*)d_in[1];
    const float* t = (const float*)d_in[2];
    float* out = (float*)d_out;

    int nrows = in_sizes[0] / 512;      // 131072

    init_tw_kernel<<<1, 512>>>();       // idempotent, graph-capturable
    hole_kernel<<<4096, 128>>>(h, r, t, out, nrows);   // 16384 warps -> 2 quads/warp
}

// round 12
// speedup vs baseline: 1.2300x; 1.2300x over previous
#include <cuda_runtime.h>
#include <math.h>

#define FULL_MASK 0xffffffffu
#define TWO_PI_F 6.28318530717958647692f

// ---------------- packed f32x2 primitives ----------------
typedef unsigned long long f2;   // two packed fp32 lanes: {lo, hi}

__device__ __forceinline__ f2 f2pack(float a, float b) {
    f2 r; asm("mov.b64 %0, {%1, %2};" : "=l"(r) : "f"(a), "f"(b)); return r;
}
__device__ __forceinline__ void f2unpack(f2 v, float& a, float& b) {
    asm("mov.b64 {%0, %1}, %2;" : "=f"(a), "=f"(b) : "l"(v));
}
__device__ __forceinline__ f2 f2add(f2 a, f2 b) {
    f2 r; asm("add.rn.f32x2 %0, %1, %2;" : "=l"(r) : "l"(a), "l"(b)); return r;
}
__device__ __forceinline__ f2 f2mul(f2 a, f2 b) {
    f2 r; asm("mul.rn.f32x2 %0, %1, %2;" : "=l"(r) : "l"(a), "l"(b)); return r;
}
__device__ __forceinline__ f2 f2fma(f2 a, f2 b, f2 c) {
    f2 r; asm("fma.rn.f32x2 %0, %1, %2, %3;" : "=l"(r) : "l"(a), "l"(b), "l"(c)); return r;
}
__device__ __forceinline__ f2 f2splat(float s) { return f2pack(s, s); }

// digit-swap permutation for radix-4 FFT16: p = 4s+q  ->  k = 4q+s
__device__ __forceinline__ constexpr int dig4c(int p) {
    return ((p & 3) << 2) | (p >> 2);
}

// four-step twiddle table: g_tw512[p*32+lane] = w512^{lane * dig4(p)}
__device__ float2 g_tw512[16 * 32];

__global__ void init_tw_kernel() {
    int e = threadIdx.x;            // 0..511
    int p  = e >> 5;
    int ln = e & 31;
    int k1 = dig4c(p);
    float ang = -(TWO_PI_F / 512.f) * (float)(ln * k1);
    float s, c;
    sincosf(ang, &s, &c);
    g_tw512[p * 32 + ln] = make_float2(c, s);
}

// complex multiply helper: (xr,xi) *= (wr,wi), compile-time w; 5 packed ops
#define CMUL_CONST(XR, XI, WR, WI, NEG) do {                         \
    f2 _wr = f2splat(WR), _wi = f2splat(WI);                         \
    f2 _t1 = f2mul(XI, _wi);                                         \
    f2 _ni = f2fma(XI, _wr, f2mul(XR, _wi));                         \
    XR = f2fma(_t1, NEG, f2mul(XR, _wr));                            \
    XI = _ni;                                                        \
} while (0)

// 4-op cmul with immediate +/-w constants (no NEG): nr = xr*wr + xi*(-wi); ni = xr*wi + xi*wr
#define CMUL_IMM4(XR, XI, WR, WI) do {                               \
    f2 _nr = f2fma(XI, f2splat(-(WI)), f2mul(XR, f2splat(WR)));      \
    f2 _ni = f2fma(XI, f2splat(WR),  f2mul(XR, f2splat(WI)));        \
    XR = _nr; XI = _ni;                                              \
} while (0)

// Per-thread radix-4 16-point DIF FFT over 16 register slots (packed: 2 FFTs).
// Input slot s = time index n. Output slot p holds bin dig4(p) = 4(p&3)+(p>>2).
__device__ __forceinline__ void fft16_r4(f2 (&xr)[16], f2 (&xi)[16], f2 NEG)
{
    const float C1 = 0.9238795325f, C2 = 0.7071067812f, C3 = 0.3826834324f;

    // ---- stage 1: radix-4 over stride-4 groups n=0..3, with w16^{n*s} twiddles
    #pragma unroll
    for (int n = 0; n < 4; ++n) {
        f2 t0r = f2add(xr[n],     xr[n + 8]), t0i = f2add(xi[n],     xi[n + 8]);
        f2 t1r = f2fma(xr[n + 8], NEG, xr[n]), t1i = f2fma(xi[n + 8], NEG, xi[n]);
        f2 t2r = f2add(xr[n + 4], xr[n + 12]), t2i = f2add(xi[n + 4], xi[n + 12]);
        f2 t3r = f2fma(xr[n + 12], NEG, xr[n + 4]), t3i = f2fma(xi[n + 12], NEG, xi[n + 4]);

        xr[n] = f2add(t0r, t2r);
        xi[n] = f2add(t0i, t2i);
        f2 u1r = f2add(t1r, t3i);
        f2 u1i = f2fma(t3r, NEG, t1i);
        f2 u2r = f2fma(t2r, NEG, t0r);
        f2 u2i = f2fma(t2i, NEG, t0i);
        f2 u3r = f2fma(t3i, NEG, t1r);
        f2 u3i = f2add(t1i, t3r);

        if (n == 1) {
            CMUL_CONST(u1r, u1i,  C1, -C3, NEG);   // w16^1
            CMUL_CONST(u2r, u2i,  C2, -C2, NEG);   // w16^2
            CMUL_CONST(u3r, u3i,  C3, -C1, NEG);   // w16^3
        } else if (n == 2) {
            CMUL_CONST(u1r, u1i,  C2, -C2, NEG);   // w16^2
            { f2 tr = u2r; u2r = u2i; u2i = f2mul(tr, NEG); }   // w16^4 = -i
            CMUL_CONST(u3r, u3i, -C2, -C2, NEG);   // w16^6
        } else if (n == 3) {
            CMUL_CONST(u1r, u1i,  C3, -C1, NEG);   // w16^3
            CMUL_CONST(u2r, u2i, -C2, -C2, NEG);   // w16^6
            CMUL_CONST(u3r, u3i, -C1,  C3, NEG);   // w16^9
        }
        xr[n + 4] = u1r;  xi[n + 4] = u1i;
        xr[n + 8] = u2r;  xi[n + 8] = u2i;
        xr[n + 12] = u3r; xi[n + 12] = u3i;
    }

    // ---- stage 2: radix-4 within each 4-slot block (no twiddles)
    #pragma unroll
    for (int s = 0; s < 4; ++s) {
        int b = 4 * s;
        f2 t0r = f2add(xr[b],     xr[b + 2]), t0i = f2add(xi[b],     xi[b + 2]);
        f2 t1r = f2fma(xr[b + 2], NEG, xr[b]), t1i = f2fma(xi[b + 2], NEG, xi[b]);
        f2 t2r = f2add(xr[b + 1], xr[b + 3]), t2i = f2add(xi[b + 1], xi[b + 3]);
        f2 t3r = f2fma(xr[b + 3], NEG, xr[b + 1]), t3i = f2fma(xi[b + 3], NEG, xi[b + 1]);

        xr[b]     = f2add(t0r, t2r);              xi[b]     = f2add(t0i, t2i);
        xr[b + 1] = f2add(t1r, t3i);              xi[b + 1] = f2fma(t3r, NEG, t1i);
        xr[b + 2] = f2fma(t2r, NEG, t0r);         xi[b + 2] = f2fma(t2i, NEG, t0i);
        xr[b + 3] = f2fma(t3i, NEG, t1r);         xi[b + 3] = f2add(t1i, t3r);
    }
}

// Full 512-point packed FFT (two independent FFTs in f2 lanes).
// Output: slot p on lane (=16*par+k1) holds bin k = lane + 32*dig4(p).
// Single-round float4 slab transpose; n3 radix-2 fused into the read; the
// odd-branch w32^{n2} twiddle runs under a divergent `if (par)` with
// immediate constants (upper half-warp only -> fewer issues, no FSEL regs).
__device__ __forceinline__ void fft512D(f2 (&xr)[16], f2 (&xi)[16],
                                        int lane, int par,
                                        ulonglong2* __restrict__ slab,
                                        f2 NEG, f2 SP)
{
    // pass 1: FFT16 over slots (n1)
    fft16_r4(xr, xi, NEG);

    // four-step twiddle: slot p *= w512^{lane * dig4(p)} (global table, L1-resident)
    #pragma unroll
    for (int p = 1; p < 16; ++p) {
        float2 w = __ldg(&g_tw512[p * 32 + lane]);
        f2 wr = f2splat(w.x), wi = f2splat(w.y);
        f2 t1 = f2mul(xi[p], wi);
        f2 ni = f2fma(xi[p], wr, f2mul(xr[p], wi));
        xr[p] = f2fma(t1, NEG, f2mul(xr[p], wr));
        xi[p] = ni;
    }

    const int wb = (lane & 15) * 33;    // read row base (pad-33 float4 rows)

    // single-round transpose: {xr,xi} as one 16B element; fold n3 radix-2 on read
    __syncwarp();
    #pragma unroll
    for (int p = 0; p < 16; ++p)
        slab[dig4c(p) * 33 + lane] = make_ulonglong2(xr[p], xi[p]);
    __syncwarp();
    #pragma unroll
    for (int s = 0; s < 16; ++s) {
        ulonglong2 y0 = slab[wb + s];
        ulonglong2 y1 = slab[wb + s + 16];
        xr[s] = f2fma((f2)y1.x, SP, (f2)y0.x);   // e (par=0) | y0-y1 (par=1)
        xi[s] = f2fma((f2)y1.y, SP, (f2)y0.y);
    }

    // odd-branch pre-twiddle: ONLY par=1 lanes execute (divergent branch with
    // immediate constants; even lanes masked -> their issue slots are saved)
    if (par) {
        CMUL_IMM4(xr[1],  xi[1],   0.98078528f, -0.19509032f);
        CMUL_IMM4(xr[2],  xi[2],   0.92387953f, -0.38268343f);
        CMUL_IMM4(xr[3],  xi[3],   0.83146961f, -0.55557023f);
        CMUL_IMM4(xr[4],  xi[4],   0.70710678f, -0.70710678f);
        CMUL_IMM4(xr[5],  xi[5],   0.55557023f, -0.83146961f);
        CMUL_IMM4(xr[6],  xi[6],   0.38268343f, -0.92387953f);
        CMUL_IMM4(xr[7],  xi[7],   0.19509032f, -0.98078528f);
        { f2 tr = xr[8]; xr[8] = xi[8]; xi[8] = f2mul(tr, NEG); }   // * -i
        CMUL_IMM4(xr[9],  xi[9],  -0.19509032f, -0.98078528f);
        CMUL_IMM4(xr[10], xi[10], -0.38268343f, -0.92387953f);
        CMUL_IMM4(xr[11], xi[11], -0.55557023f, -0.83146961f);
        CMUL_IMM4(xr[12], xi[12], -0.70710678f, -0.70710678f);
        CMUL_IMM4(xr[13], xi[13], -0.83146961f, -0.55557023f);
        CMUL_IMM4(xr[14], xi[14], -0.92387953f, -0.38268343f);
        CMUL_IMM4(xr[15], xi[15], -0.98078528f, -0.19509032f);
    }

    // pass 2: FFT16 over n2 -> k2 = 2*dig4(slot) + par
    fft16_r4(xr, xi, NEG);
}

// out[b] = Im( sum_f Z[f]^2 * conj(T[f]) ) / (2*D), Z = FFT(h+ir), T = FFT(t).
// Packed per row: lo = Z-FFT, hi = T-FFT. Persistent grid (4 blocks/SM resident),
// with L2 prefetch of the NEXT row's 48 cache lines issued each iteration.
__global__ void __launch_bounds__(128, 4)
hole_kernel(const float* __restrict__ h, const float* __restrict__ r,
            const float* __restrict__ t, float* __restrict__ out, int nrows)
{
    const int lane = threadIdx.x & 31;
    const int wid  = threadIdx.x >> 5;
    const int warp = blockIdx.x * 4 + wid;
    const int nw   = gridDim.x * 4;
    const int par  = lane >> 4;

    __shared__ ulonglong2 slab_s[4][16 * 33];   // 8.25 KB/warp float4 slab
    ulonglong2* __restrict__ slab = slab_s[wid];

    const f2 NEG = f2splat(-1.f);
    const f2 SP  = f2splat(par ? -1.f : 1.f);

    for (int row = warp; row < nrows; row += nw) {
        size_t base = (size_t)row * 512 + (size_t)lane;
        const float* hp = h + base;
        const float* rp = r + base;
        const float* tp = t + base;

        // coalesced loads; lo = Z input (h + i r), hi = T input (t + i 0)
        f2 xr[16], xi[16];
        #pragma unroll
        for (int s = 0; s < 16; ++s) {
            float hv = hp[32 * s];
            float tv = tp[32 * s];
            float rv = rp[32 * s];
            xr[s] = f2pack(hv, tv);
            xi[s] = f2pack(rv, 0.f);
        }

        // prefetch next row's 48 x 128B lines to L2 (lane-partitioned, no regs held)
        {
            int nrow = row + nw;
            if (nrow < nrows) {
                size_t nb = (size_t)nrow * 512;
                size_t lo = (size_t)((lane & 15) * 32);
                const float* p0 = par ? (r + nb + lo) : (h + nb + lo);
                const float* p1 = t + nb + lo;
                asm volatile("prefetch.global.L2 [%0];" :: "l"(p0));
                asm volatile("prefetch.global.L2 [%0];" :: "l"(p1));
            }
        }

        fft512D(xr, xi, lane, par, slab, NEG, SP);

        // acc = sum over this lane's 16 bins of Im(Z^2 * conj(T))
        float acc = 0.f;
        #pragma unroll
        for (int s = 0; s < 16; ++s) {
            float a, tr, b, ti;
            f2unpack(xr[s], a, tr);    // lo = Re Z, hi = Re T
            f2unpack(xi[s], b, ti);    // lo = Im Z, hi = Im T
            float im2 = 2.f * a * b;               // Im(Z^2)
            float re2 = a * a - b * b;             // Re(Z^2)
            acc = fmaf(im2, tr, acc);
            acc = fmaf(-re2, ti, acc);
        }
        #pragma unroll
        for (int o = 16; o; o >>= 1)
            acc += __shfl_xor_sync(FULL_MASK, acc, o);

        if (lane == 0) out[row] = acc * (1.f / 1024.f);   // 1/(2*D)
    }
}

extern "C" void kernel_launch(void* const* d_in, const int* in_sizes, int n_in,
                              void* d_out, int out_size)
{
    const float* h = (const float*)d_in[0];
    const float* r = (const float*)d_in[1];
    const float* t = (const float*)d_in[2];
    float* out = (float*)d_out;

    int nrows = in_sizes[0] / 512;      // 131072

    init_tw_kernel<<<1, 512>>>();       // idempotent, graph-capturable
    // persistent: 592 blocks = 148 SMs x 4 resident blocks; each warp ~55 rows
    hole_kernel<<<592, 128>>>(h, r, t, out, nrows);
}

// round 13
// speedup vs baseline: 1.3692x; 1.1132x over previous
#include <cuda_runtime.h>
#include <math.h>

#define FULL_MASK 0xffffffffu
#define TWO_PI_F 6.28318530717958647692f

// ---------------- packed f32x2 primitives ----------------
typedef unsigned long long f2;   // two packed fp32 lanes: {lo, hi}

__device__ __forceinline__ f2 f2pack(float a, float b) {
    f2 r; asm("mov.b64 %0, {%1, %2};" : "=l"(r) : "f"(a), "f"(b)); return r;
}
__device__ __forceinline__ void f2unpack(f2 v, float& a, float& b) {
    asm("mov.b64 {%0, %1}, %2;" : "=f"(a), "=f"(b) : "l"(v));
}
__device__ __forceinline__ f2 f2add(f2 a, f2 b) {
    f2 r; asm("add.rn.f32x2 %0, %1, %2;" : "=l"(r) : "l"(a), "l"(b)); return r;
}
__device__ __forceinline__ f2 f2mul(f2 a, f2 b) {
    f2 r; asm("mul.rn.f32x2 %0, %1, %2;" : "=l"(r) : "l"(a), "l"(b)); return r;
}
__device__ __forceinline__ f2 f2fma(f2 a, f2 b, f2 c) {
    f2 r; asm("fma.rn.f32x2 %0, %1, %2, %3;" : "=l"(r) : "l"(a), "l"(b), "l"(c)); return r;
}
__device__ __forceinline__ f2 f2splat(float s) { return f2pack(s, s); }

// digit-swap permutation for radix-4 FFT16: p = 4s+q  ->  k = 4q+s
__device__ __forceinline__ constexpr int dig4c(int p) {
    return ((p & 3) << 2) | (p >> 2);
}

// four-step twiddle table: g_tw512[p*32+lane] = w512^{lane * dig4(p)}
__device__ float2 g_tw512[16 * 32];

__global__ void init_tw_kernel() {
    int e = threadIdx.x;            // 0..511
    int p  = e >> 5;
    int ln = e & 31;
    int k1 = dig4c(p);
    float ang = -(TWO_PI_F / 512.f) * (float)(ln * k1);
    float s, c;
    sincosf(ang, &s, &c);
    g_tw512[p * 32 + ln] = make_float2(c, s);
}

// complex multiply helper: (xr,xi) *= (wr,wi), compile-time w; 5 packed ops
#define CMUL_CONST(XR, XI, WR, WI, NEG) do {                         \
    f2 _wr = f2splat(WR), _wi = f2splat(WI);                         \
    f2 _t1 = f2mul(XI, _wi);                                         \
    f2 _ni = f2fma(XI, _wr, f2mul(XR, _wi));                         \
    XR = f2fma(_t1, NEG, f2mul(XR, _wr));                            \
    XI = _ni;                                                        \
} while (0)

// Per-thread radix-4 16-point DIF FFT over 16 register slots (packed: 2 FFTs).
// Input slot s = time index n. Output slot p holds bin dig4(p) = 4(p&3)+(p>>2).
__device__ __forceinline__ void fft16_r4(f2 (&xr)[16], f2 (&xi)[16], f2 NEG)
{
    const float C1 = 0.9238795325f, C2 = 0.7071067812f, C3 = 0.3826834324f;

    // ---- stage 1: radix-4 over stride-4 groups n=0..3, with w16^{n*s} twiddles
    #pragma unroll
    for (int n = 0; n < 4; ++n) {
        f2 t0r = f2add(xr[n],     xr[n + 8]), t0i = f2add(xi[n],     xi[n + 8]);
        f2 t1r = f2fma(xr[n + 8], NEG, xr[n]), t1i = f2fma(xi[n + 8], NEG, xi[n]);
        f2 t2r = f2add(xr[n + 4], xr[n + 12]), t2i = f2add(xi[n + 4], xi[n + 12]);
        f2 t3r = f2fma(xr[n + 12], NEG, xr[n + 4]), t3i = f2fma(xi[n + 12], NEG, xi[n + 4]);

        xr[n] = f2add(t0r, t2r);
        xi[n] = f2add(t0i, t2i);
        f2 u1r = f2add(t1r, t3i);
        f2 u1i = f2fma(t3r, NEG, t1i);
        f2 u2r = f2fma(t2r, NEG, t0r);
        f2 u2i = f2fma(t2i, NEG, t0i);
        f2 u3r = f2fma(t3i, NEG, t1r);
        f2 u3i = f2add(t1i, t3r);

        if (n == 1) {
            CMUL_CONST(u1r, u1i,  C1, -C3, NEG);   // w16^1
            CMUL_CONST(u2r, u2i,  C2, -C2, NEG);   // w16^2
            CMUL_CONST(u3r, u3i,  C3, -C1, NEG);   // w16^3
        } else if (n == 2) {
            CMUL_CONST(u1r, u1i,  C2, -C2, NEG);   // w16^2
            { f2 tr = u2r; u2r = u2i; u2i = f2mul(tr, NEG); }   // w16^4 = -i
            CMUL_CONST(u3r, u3i, -C2, -C2, NEG);   // w16^6
        } else if (n == 3) {
            CMUL_CONST(u1r, u1i,  C3, -C1, NEG);   // w16^3
            CMUL_CONST(u2r, u2i, -C2, -C2, NEG);   // w16^6
            CMUL_CONST(u3r, u3i, -C1,  C3, NEG);   // w16^9
        }
        xr[n + 4] = u1r;  xi[n + 4] = u1i;
        xr[n + 8] = u2r;  xi[n + 8] = u2i;
        xr[n + 12] = u3r; xi[n + 12] = u3i;
    }

    // ---- stage 2: radix-4 within each 4-slot block (no twiddles)
    #pragma unroll
    for (int s = 0; s < 4; ++s) {
        int b = 4 * s;
        f2 t0r = f2add(xr[b],     xr[b + 2]), t0i = f2add(xi[b],     xi[b + 2]);
        f2 t1r = f2fma(xr[b + 2], NEG, xr[b]), t1i = f2fma(xi[b + 2], NEG, xi[b]);
        f2 t2r = f2add(xr[b + 1], xr[b + 3]), t2i = f2add(xi[b + 1], xi[b + 3]);
        f2 t3r = f2fma(xr[b + 3], NEG, xr[b + 1]), t3i = f2fma(xi[b + 3], NEG, xi[b + 1]);

        xr[b]     = f2add(t0r, t2r);              xi[b]     = f2add(t0i, t2i);
        xr[b + 1] = f2add(t1r, t3i);              xi[b + 1] = f2fma(t3r, NEG, t1i);
        xr[b + 2] = f2fma(t2r, NEG, t0r);         xi[b + 2] = f2fma(t2i, NEG, t0i);
        xr[b + 3] = f2fma(t3i, NEG, t1r);         xi[b + 3] = f2add(t1i, t3r);
    }
}

// Full 512-point packed FFT (two independent FFTs in f2 lanes).
// Output: slot p on lane (=16*par+k1) holds bin k = lane + 32*dig4(p).
// Single-round float4 slab transpose with the n3 radix-2 AND the w32^{n2}
// odd-branch twiddle both folded into the read (FSEL'd constants, no branch).
__device__ __forceinline__ void fft512D(f2 (&xr)[16], f2 (&xi)[16],
                                        int lane, int par,
                                        ulonglong2* __restrict__ slab,
                                        f2 NEG, f2 SP)
{
    constexpr float W32R_[16] = {
        1.f, 0.98078528f, 0.92387953f, 0.83146961f, 0.70710678f, 0.55557023f,
        0.38268343f, 0.19509032f, 0.f, -0.19509032f, -0.38268343f, -0.55557023f,
        -0.70710678f, -0.83146961f, -0.92387953f, -0.98078528f };
    constexpr float W32I_[16] = {
        0.f, -0.19509032f, -0.38268343f, -0.55557023f, -0.70710678f, -0.83146961f,
        -0.92387953f, -0.98078528f, -1.f, -0.98078528f, -0.92387953f, -0.83146961f,
        -0.70710678f, -0.55557023f, -0.38268343f, -0.19509032f };

    // pass 1: FFT16 over slots (n1)
    fft16_r4(xr, xi, NEG);

    // four-step twiddle: slot p *= w512^{lane * dig4(p)} (global table, L1-resident)
    #pragma unroll
    for (int p = 1; p < 16; ++p) {
        float2 w = __ldg(&g_tw512[p * 32 + lane]);
        f2 wr = f2splat(w.x), wi = f2splat(w.y);
        f2 t1 = f2mul(xi[p], wi);
        f2 ni = f2fma(xi[p], wr, f2mul(xr[p], wi));
        xr[p] = f2fma(t1, NEG, f2mul(xr[p], wr));
        xi[p] = ni;
    }

    const int wb = (lane & 15) * 33;    // read row base (pad-33 float4 rows)

    // single-round transpose: {xr,xi} as one 16B element; fold n3 radix-2 and
    // odd-branch w32^{n2} twiddle into the read:
    //   par=0: x = y0 + y1
    //   par=1: x = (y0 - y1) * w32^{s}
    __syncwarp();
    #pragma unroll
    for (int p = 0; p < 16; ++p)
        slab[dig4c(p) * 33 + lane] = make_ulonglong2(xr[p], xi[p]);
    __syncwarp();
    #pragma unroll
    for (int s = 0; s < 16; ++s) {
        ulonglong2 y0 = slab[wb + s];
        ulonglong2 y1 = slab[wb + s + 16];
        f2 dr = f2fma((f2)y1.x, SP, (f2)y0.x);   // y0r +/- y1r
        f2 di = f2fma((f2)y1.y, SP, (f2)y0.y);
        if (s == 0) {
            xr[0] = dr; xi[0] = di;
        } else {
            float cr  = par ? W32R_[s] : 1.f;    // FSEL (alu pipe)
            float ci  = par ? W32I_[s] : 0.f;
            float cin = par ? -W32I_[s] : 0.f;
            f2 wr = f2splat(cr), wi = f2splat(ci), win = f2splat(cin);
            xr[s] = f2fma(di, win, f2mul(dr, wr));
            xi[s] = f2fma(di, wr,  f2mul(dr, wi));
        }
    }

    // pass 2: FFT16 over n2 -> k2 = 2*dig4(slot) + par
    fft16_r4(xr, xi, NEG);
}

// out[b] = Im( sum_f Z[f]^2 * conj(T[f]) ) / (2*D), Z = FFT(h+ir), T = FFT(t).
// Packed per row: lo = Z-FFT, hi = T-FFT. Independent rows -> full pipelining.
// Single change vs the 172us baseline: L2-prefetch the NEXT row's cache lines.
__global__ void __launch_bounds__(128, 4)
hole_kernel(const float* __restrict__ h, const float* __restrict__ r,
            const float* __restrict__ t, float* __restrict__ out, int nrows)
{
    const int lane = threadIdx.x & 31;
    const int wid  = threadIdx.x >> 5;
    const int warp = blockIdx.x * 4 + wid;
    const int nw   = gridDim.x * 4;
    const int par  = lane >> 4;

    __shared__ ulonglong2 slab_s[4][16 * 33];   // 8.25 KB/warp float4 slab
    ulonglong2* __restrict__ slab = slab_s[wid];

    const f2 NEG = f2splat(-1.f);
    const f2 SP  = f2splat(par ? -1.f : 1.f);

    for (int row = warp; row < nrows; row += nw) {
        size_t base = (size_t)row * 512 + (size_t)lane;
        const float* hp = h + base;
        const float* rp = r + base;
        const float* tp = t + base;

        // coalesced loads; lo = Z input (h + i r), hi = T input (t + i 0)
        f2 xr[16], xi[16];
        #pragma unroll
        for (int s = 0; s < 16; ++s) {
            float hv = hp[32 * s];
            float tv = tp[32 * s];
            float rv = rp[32 * s];
            xr[s] = f2pack(hv, tv);
            xi[s] = f2pack(rv, 0.f);
        }

        // prefetch next row's 48 x 128B lines to L2 (lane-partitioned: 16 lanes
        // cover one array's 16 lines; par selects h vs r; all lanes cover t)
        {
            int nrow = row + nw;
            if (nrow < nrows) {
                size_t nb = (size_t)nrow * 512 + (size_t)((lane & 15) * 32);
                const float* p0 = par ? (r + nb) : (h + nb);
                const float* p1 = t + nb;
                asm volatile("prefetch.global.L2 [%0];" :: "l"(p0));
                asm volatile("prefetch.global.L2 [%0];" :: "l"(p1));
            }
        }

        fft512D(xr, xi, lane, par, slab, NEG, SP);

        // acc = sum over this lane's 16 bins of Im(Z^2 * conj(T))
        float acc = 0.f;
        #pragma unroll
        for (int s = 0; s < 16; ++s) {
            float a, tr, b, ti;
            f2unpack(xr[s], a, tr);    // lo = Re Z, hi = Re T
            f2unpack(xi[s], b, ti);    // lo = Im Z, hi = Im T
            float im2 = 2.f * a * b;               // Im(Z^2)
            float re2 = a * a - b * b;             // Re(Z^2)
            acc = fmaf(im2, tr, acc);
            acc = fmaf(-re2, ti, acc);
        }
        #pragma unroll
        for (int o = 16; o; o >>= 1)
            acc += __shfl_xor_sync(FULL_MASK, acc, o);

        if (lane == 0) out[row] = acc * (1.f / 1024.f);   // 1/(2*D)
    }
}

extern "C" void kernel_launch(void* const* d_in, const int* in_sizes, int n_in,
                              void* d_out, int out_size)
{
    const float* h = (const float*)d_in[0];
    const float* r = (const float*)d_in[1];
    const float* t = (const float*)d_in[2];
    float* out = (float*)d_out;

    int nrows = in_sizes[0] / 512;      // 131072

    init_tw_kernel<<<1, 512>>>();       // idempotent, graph-capturable
    hole_kernel<<<4096, 128>>>(h, r, t, out, nrows);   // 16384 warps -> 8 rows/warp
}

// round 14
// speedup vs baseline: 1.3964x; 1.0198x over previous
#include <cuda_runtime.h>
#include <math.h>

#define FULL_MASK 0xffffffffu
#define TWO_PI_F 6.28318530717958647692f

// ---------------- packed f32x2 primitives ----------------
typedef unsigned long long f2;   // two packed fp32 lanes: {lo, hi}

__device__ __forceinline__ f2 f2pack(float a, float b) {
    f2 r; asm("mov.b64 %0, {%1, %2};" : "=l"(r) : "f"(a), "f"(b)); return r;
}
__device__ __forceinline__ void f2unpack(f2 v, float& a, float& b) {
    asm("mov.b64 {%0, %1}, %2;" : "=f"(a), "=f"(b) : "l"(v));
}
__device__ __forceinline__ f2 f2add(f2 a, f2 b) {
    f2 r; asm("add.rn.f32x2 %0, %1, %2;" : "=l"(r) : "l"(a), "l"(b)); return r;
}
__device__ __forceinline__ f2 f2mul(f2 a, f2 b) {
    f2 r; asm("mul.rn.f32x2 %0, %1, %2;" : "=l"(r) : "l"(a), "l"(b)); return r;
}
__device__ __forceinline__ f2 f2fma(f2 a, f2 b, f2 c) {
    f2 r; asm("fma.rn.f32x2 %0, %1, %2, %3;" : "=l"(r) : "l"(a), "l"(b), "l"(c)); return r;
}
__device__ __forceinline__ f2 f2splat(float s) { return f2pack(s, s); }

// digit-swap permutation for radix-4 FFT16: p = 4s+q  ->  k = 4q+s
__device__ __forceinline__ constexpr int dig4c(int p) {
    return ((p & 3) << 2) | (p >> 2);
}

// four-step twiddle table: g_tw512[p*32+lane] = w512^{lane * dig4(p)}
__device__ float2 g_tw512[16 * 32];

__global__ void init_tw_kernel() {
    int e = threadIdx.x;            // 0..511
    int p  = e >> 5;
    int ln = e & 31;
    int k1 = dig4c(p);
    float ang = -(TWO_PI_F / 512.f) * (float)(ln * k1);
    float s, c;
    sincosf(ang, &s, &c);
    g_tw512[p * 32 + ln] = make_float2(c, s);
}

// 4-op cmul with immediate +/-w constants: re = xr*WR - xi*WI; im = xr*WI + xi*WR
#define CMUL_IMM4(XR, XI, WR, WI) do {                               \
    f2 _nr = f2fma(XI, f2splat(-(WI)), f2mul(XR, f2splat(WR)));      \
    f2 _ni = f2fma(XI, f2splat(WR),  f2mul(XR, f2splat(WI)));        \
    XR = _nr; XI = _ni;                                              \
} while (0)

// Per-thread radix-4 16-point DIF FFT over 16 register slots (packed: 2 FFTs).
// Input slot s = time index n. Output slot p holds bin dig4(p) = 4(p&3)+(p>>2).
__device__ __forceinline__ void fft16_r4(f2 (&xr)[16], f2 (&xi)[16], f2 NEG)
{
    const float C1 = 0.9238795325f, C2 = 0.7071067812f, C3 = 0.3826834324f;

    // ---- stage 1: radix-4 over stride-4 groups n=0..3, with w16^{n*s} twiddles
    #pragma unroll
    for (int n = 0; n < 4; ++n) {
        f2 t0r = f2add(xr[n],     xr[n + 8]), t0i = f2add(xi[n],     xi[n + 8]);
        f2 t1r = f2fma(xr[n + 8], NEG, xr[n]), t1i = f2fma(xi[n + 8], NEG, xi[n]);
        f2 t2r = f2add(xr[n + 4], xr[n + 12]), t2i = f2add(xi[n + 4], xi[n + 12]);
        f2 t3r = f2fma(xr[n + 12], NEG, xr[n + 4]), t3i = f2fma(xi[n + 12], NEG, xi[n + 4]);

        xr[n] = f2add(t0r, t2r);
        xi[n] = f2add(t0i, t2i);
        f2 u1r = f2add(t1r, t3i);
        f2 u1i = f2fma(t3r, NEG, t1i);
        f2 u2r = f2fma(t2r, NEG, t0r);
        f2 u2i = f2fma(t2i, NEG, t0i);
        f2 u3r = f2fma(t3i, NEG, t1r);
        f2 u3i = f2add(t1i, t3r);

        if (n == 1) {
            CMUL_IMM4(u1r, u1i,  C1, -C3);   // w16^1
            CMUL_IMM4(u2r, u2i,  C2, -C2);   // w16^2
            CMUL_IMM4(u3r, u3i,  C3, -C1);   // w16^3
        } else if (n == 2) {
            CMUL_IMM4(u1r, u1i,  C2, -C2);   // w16^2
            { f2 tr = u2r; u2r = u2i; u2i = f2mul(tr, NEG); }   // w16^4 = -i
            CMUL_IMM4(u3r, u3i, -C2, -C2);   // w16^6
        } else if (n == 3) {
            CMUL_IMM4(u1r, u1i,  C3, -C1);   // w16^3
            CMUL_IMM4(u2r, u2i, -C2, -C2);   // w16^6
            CMUL_IMM4(u3r, u3i, -C1,  C3);   // w16^9
        }
        xr[n + 4] = u1r;  xi[n + 4] = u1i;
        xr[n + 8] = u2r;  xi[n + 8] = u2i;
        xr[n + 12] = u3r; xi[n + 12] = u3i;
    }

    // ---- stage 2: radix-4 within each 4-slot block (no twiddles)
    #pragma unroll
    for (int s = 0; s < 4; ++s) {
        int b = 4 * s;
        f2 t0r = f2add(xr[b],     xr[b + 2]), t0i = f2add(xi[b],     xi[b + 2]);
        f2 t1r = f2fma(xr[b + 2], NEG, xr[b]), t1i = f2fma(xi[b + 2], NEG, xi[b]);
        f2 t2r = f2add(xr[b + 1], xr[b + 3]), t2i = f2add(xi[b + 1], xi[b + 3]);
        f2 t3r = f2fma(xr[b + 3], NEG, xr[b + 1]), t3i = f2fma(xi[b + 3], NEG, xi[b + 1]);

        xr[b]     = f2add(t0r, t2r);              xi[b]     = f2add(t0i, t2i);
        xr[b + 1] = f2add(t1r, t3i);              xi[b + 1] = f2fma(t3r, NEG, t1i);
        xr[b + 2] = f2fma(t2r, NEG, t0r);         xi[b + 2] = f2fma(t2i, NEG, t0i);
        xr[b + 3] = f2fma(t3i, NEG, t1r);         xi[b + 3] = f2add(t1i, t3r);
    }
}

// Full 512-point packed FFT (two independent FFTs in f2 lanes).
// Output: slot p on lane (=16*par+k1) holds bin k = lane + 32*dig4(p).
// Single-round float4 slab transpose with the n3 radix-2 AND the w32^{n2}
// odd-branch twiddle both folded into the read (FSEL'd constants, no branch).
__device__ __forceinline__ void fft512D(f2 (&xr)[16], f2 (&xi)[16],
                                        int lane, int par,
                                        ulonglong2* __restrict__ slab,
                                        f2 NEG, f2 SP)
{
    constexpr float W32R_[16] = {
        1.f, 0.98078528f, 0.92387953f, 0.83146961f, 0.70710678f, 0.55557023f,
        0.38268343f, 0.19509032f, 0.f, -0.19509032f, -0.38268343f, -0.55557023f,
        -0.70710678f, -0.83146961f, -0.92387953f, -0.98078528f };
    constexpr float W32I_[16] = {
        0.f, -0.19509032f, -0.38268343f, -0.55557023f, -0.70710678f, -0.83146961f,
        -0.92387953f, -0.98078528f, -1.f, -0.98078528f, -0.92387953f, -0.83146961f,
        -0.70710678f, -0.55557023f, -0.38268343f, -0.19509032f };

    // pass 1: FFT16 over slots (n1)
    fft16_r4(xr, xi, NEG);

    // four-step twiddle: slot p *= w512^{lane * dig4(p)} (global table, L1-resident)
    #pragma unroll
    for (int p = 1; p < 16; ++p) {
        float2 w = __ldg(&g_tw512[p * 32 + lane]);
        f2 wr = f2splat(w.x), wi = f2splat(w.y);
        f2 t1 = f2mul(xi[p], wi);
        f2 ni = f2fma(xi[p], wr, f2mul(xr[p], wi));
        xr[p] = f2fma(t1, NEG, f2mul(xr[p], wr));
        xi[p] = ni;
    }

    const int wb = (lane & 15) * 33;    // read row base (pad-33 float4 rows)

    // single-round transpose: {xr,xi} as one 16B element; fold n3 radix-2 and
    // odd-branch w32^{n2} twiddle into the read:
    //   par=0: x = y0 + y1
    //   par=1: x = (y0 - y1) * w32^{s}
    __syncwarp();
    #pragma unroll
    for (int p = 0; p < 16; ++p)
        slab[dig4c(p) * 33 + lane] = make_ulonglong2(xr[p], xi[p]);
    __syncwarp();
    #pragma unroll
    for (int s = 0; s < 16; ++s) {
        ulonglong2 y0 = slab[wb + s];
        ulonglong2 y1 = slab[wb + s + 16];
        f2 dr = f2fma((f2)y1.x, SP, (f2)y0.x);   // y0r +/- y1r
        f2 di = f2fma((f2)y1.y, SP, (f2)y0.y);
        if (s == 0) {
            xr[0] = dr; xi[0] = di;
        } else {
            float cr  = par ? W32R_[s] : 1.f;    // FSEL (alu pipe)
            float ci  = par ? W32I_[s] : 0.f;
            float cin = par ? -W32I_[s] : 0.f;
            f2 wr = f2splat(cr), wi = f2splat(ci), win = f2splat(cin);
            xr[s] = f2fma(di, win, f2mul(dr, wr));
            xi[s] = f2fma(di, wr,  f2mul(dr, wi));
        }
    }

    // pass 2: FFT16 over n2 -> k2 = 2*dig4(slot) + par
    fft16_r4(xr, xi, NEG);
}

// out[b] = Im( sum_f Z[f]^2 * conj(T[f]) ) / (2*D), Z = FFT(h+ir), T = FFT(t).
// Packed per row: lo = Z-FFT, hi = T-FFT. Independent rows -> full pipelining.
// L2-prefetch of the next row's lines (t prefetch deduplicated to lanes < 16).
__global__ void __launch_bounds__(128, 4)
hole_kernel(const float* __restrict__ h, const float* __restrict__ r,
            const float* __restrict__ t, float* __restrict__ out, int nrows)
{
    const int lane = threadIdx.x & 31;
    const int wid  = threadIdx.x >> 5;
    const int warp = blockIdx.x * 4 + wid;
    const int nw   = gridDim.x * 4;
    const int par  = lane >> 4;

    __shared__ ulonglong2 slab_s[4][16 * 33];   // 8.25 KB/warp float4 slab
    ulonglong2* __restrict__ slab = slab_s[wid];

    const f2 NEG = f2splat(-1.f);
    const f2 SP  = f2splat(par ? -1.f : 1.f);

    for (int row = warp; row < nrows; row += nw) {
        size_t base = (size_t)row * 512 + (size_t)lane;
        const float* hp = h + base;
        const float* rp = r + base;
        const float* tp = t + base;

        // coalesced loads; lo = Z input (h + i r), hi = T input (t + i 0)
        f2 xr[16], xi[16];
        #pragma unroll
        for (int s = 0; s < 16; ++s) {
            float hv = hp[32 * s];
            float tv = tp[32 * s];
            float rv = rp[32 * s];
            xr[s] = f2pack(hv, tv);
            xi[s] = f2pack(rv, 0.f);
        }

        // prefetch next row's 48 x 128B lines to L2:
        //   instr 1: lanes 0-15 cover h lines, lanes 16-31 cover r lines
        //   instr 2: lanes 0-15 cover t lines (upper lanes predicated off)
        {
            int nrow = row + nw;
            if (nrow < nrows) {
                size_t nb = (size_t)nrow * 512 + (size_t)((lane & 15) * 32);
                const float* p0 = par ? (r + nb) : (h + nb);
                asm volatile("prefetch.global.L2 [%0];" :: "l"(p0));
                if (!par) {
                    const float* p1 = t + nb;
                    asm volatile("prefetch.global.L2 [%0];" :: "l"(p1));
                }
            }
        }

        fft512D(xr, xi, lane, par, slab, NEG, SP);

        // reduction: out = 2*sum(ab*tr) - sum((a^2-b^2)*ti), factor 2 hoisted.
        // Two accumulator pairs (even/odd slots) to shorten dependency chains.
        float accA0 = 0.f, accA1 = 0.f, accB0 = 0.f, accB1 = 0.f;
        #pragma unroll
        for (int s = 0; s < 16; ++s) {
            float a, tr, b, ti;
            f2unpack(xr[s], a, tr);    // lo = Re Z, hi = Re T
            f2unpack(xi[s], b, ti);    // lo = Im Z, hi = Im T
            float ab  = a * b;
            float b2  = b * b;
            float re2 = fmaf(a, a, -b2);           // a^2 - b^2 (neg folds into FFMA)
            if (s & 1) { accA1 = fmaf(ab, tr, accA1); accB1 = fmaf(re2, ti, accB1); }
            else       { accA0 = fmaf(ab, tr, accA0); accB0 = fmaf(re2, ti, accB0); }
        }
        float acc = fmaf(2.f, accA0 + accA1, -(accB0 + accB1));

        #pragma unroll
        for (int o = 16; o; o >>= 1)
            acc += __shfl_xor_sync(FULL_MASK, acc, o);

        if (lane == 0) out[row] = acc * (1.f / 1024.f);   // 1/(2*D)
    }
}

extern "C" void kernel_launch(void* const* d_in, const int* in_sizes, int n_in,
                              void* d_out, int out_size)
{
    const float* h = (const float*)d_in[0];
    const float* r = (const float*)d_in[1];
    const float* t = (const float*)d_in[2];
    float* out = (float*)d_out;

    int nrows = in_sizes[0] / 512;      // 131072

    init_tw_kernel<<<1, 512>>>();       // idempotent, graph-capturable
    hole_kernel<<<4096, 128>>>(h, r, t, out, nrows);   // 16384 warps -> 8 rows/warp
}

// round 15
// speedup vs baseline: 1.3986x; 1.0016x over previous
#include <cuda_runtime.h>
#include <math.h>

#define FULL_MASK 0xffffffffu
#define TWO_PI_F 6.28318530717958647692f

// ---------------- packed f32x2 primitives ----------------
typedef unsigned long long f2;   // two packed fp32 lanes: {lo, hi}

__device__ __forceinline__ f2 f2pack(float a, float b) {
    f2 r; asm("mov.b64 %0, {%1, %2};" : "=l"(r) : "f"(a), "f"(b)); return r;
}
__device__ __forceinline__ void f2unpack(f2 v, float& a, float& b) {
    asm("mov.b64 {%0, %1}, %2;" : "=f"(a), "=f"(b) : "l"(v));
}
__device__ __forceinline__ f2 f2add(f2 a, f2 b) {
    f2 r; asm("add.rn.f32x2 %0, %1, %2;" : "=l"(r) : "l"(a), "l"(b)); return r;
}
__device__ __forceinline__ f2 f2mul(f2 a, f2 b) {
    f2 r; asm("mul.rn.f32x2 %0, %1, %2;" : "=l"(r) : "l"(a), "l"(b)); return r;
}
__device__ __forceinline__ f2 f2fma(f2 a, f2 b, f2 c) {
    f2 r; asm("fma.rn.f32x2 %0, %1, %2, %3;" : "=l"(r) : "l"(a), "l"(b), "l"(c)); return r;
}
__device__ __forceinline__ f2 f2splat(float s) { return f2pack(s, s); }

// digit-swap permutation for radix-4 FFT16: p = 4s+q  ->  k = 4q+s
__device__ __forceinline__ constexpr int dig4c(int p) {
    return ((p & 3) << 2) | (p >> 2);
}

// four-step twiddle table: g_tw512[p*32+lane] = w512^{lane * dig4(p)}
__device__ float2 g_tw512[16 * 32];

__global__ void init_tw_kernel() {
    int e = threadIdx.x;            // 0..511
    int p  = e >> 5;
    int ln = e & 31;
    int k1 = dig4c(p);
    float ang = -(TWO_PI_F / 512.f) * (float)(ln * k1);
    float s, c;
    sincosf(ang, &s, &c);
    g_tw512[p * 32 + ln] = make_float2(c, s);
}

// 4-op cmul with immediate +/-w constants: re = xr*WR - xi*WI; im = xr*WI + xi*WR
#define CMUL_IMM4(XR, XI, WR, WI) do {                               \
    f2 _nr = f2fma(XI, f2splat(-(WI)), f2mul(XR, f2splat(WR)));      \
    f2 _ni = f2fma(XI, f2splat(WR),  f2mul(XR, f2splat(WI)));        \
    XR = _nr; XI = _ni;                                              \
} while (0)

// Per-thread radix-4 16-point DIF FFT over 16 register slots (packed: 2 FFTs).
// Input slot s = time index n. Output slot p holds bin dig4(p) = 4(p&3)+(p>>2).
__device__ __forceinline__ void fft16_r4(f2 (&xr)[16], f2 (&xi)[16], f2 NEG)
{
    const float C1 = 0.9238795325f, C2 = 0.7071067812f, C3 = 0.3826834324f;

    // ---- stage 1: radix-4 over stride-4 groups n=0..3, with w16^{n*s} twiddles
    #pragma unroll
    for (int n = 0; n < 4; ++n) {
        f2 t0r = f2add(xr[n],     xr[n + 8]), t0i = f2add(xi[n],     xi[n + 8]);
        f2 t1r = f2fma(xr[n + 8], NEG, xr[n]), t1i = f2fma(xi[n + 8], NEG, xi[n]);
        f2 t2r = f2add(xr[n + 4], xr[n + 12]), t2i = f2add(xi[n + 4], xi[n + 12]);
        f2 t3r = f2fma(xr[n + 12], NEG, xr[n + 4]), t3i = f2fma(xi[n + 12], NEG, xi[n + 4]);

        xr[n] = f2add(t0r, t2r);
        xi[n] = f2add(t0i, t2i);
        f2 u1r = f2add(t1r, t3i);
        f2 u1i = f2fma(t3r, NEG, t1i);
        f2 u2r = f2fma(t2r, NEG, t0r);
        f2 u2i = f2fma(t2i, NEG, t0i);
        f2 u3r = f2fma(t3i, NEG, t1r);
        f2 u3i = f2add(t1i, t3r);

        if (n == 1) {
            CMUL_IMM4(u1r, u1i,  C1, -C3);   // w16^1
            CMUL_IMM4(u2r, u2i,  C2, -C2);   // w16^2
            CMUL_IMM4(u3r, u3i,  C3, -C1);   // w16^3
        } else if (n == 2) {
            CMUL_IMM4(u1r, u1i,  C2, -C2);   // w16^2
            { f2 tr = u2r; u2r = u2i; u2i = f2mul(tr, NEG); }   // w16^4 = -i
            CMUL_IMM4(u3r, u3i, -C2, -C2);   // w16^6
        } else if (n == 3) {
            CMUL_IMM4(u1r, u1i,  C3, -C1);   // w16^3
            CMUL_IMM4(u2r, u2i, -C2, -C2);   // w16^6
            CMUL_IMM4(u3r, u3i, -C1,  C3);   // w16^9
        }
        xr[n + 4] = u1r;  xi[n + 4] = u1i;
        xr[n + 8] = u2r;  xi[n + 8] = u2i;
        xr[n + 12] = u3r; xi[n + 12] = u3i;
    }

    // ---- stage 2: radix-4 within each 4-slot block (no twiddles)
    #pragma unroll
    for (int s = 0; s < 4; ++s) {
        int b = 4 * s;
        f2 t0r = f2add(xr[b],     xr[b + 2]), t0i = f2add(xi[b],     xi[b + 2]);
        f2 t1r = f2fma(xr[b + 2], NEG, xr[b]), t1i = f2fma(xi[b + 2], NEG, xi[b]);
        f2 t2r = f2add(xr[b + 1], xr[b + 3]), t2i = f2add(xi[b + 1], xi[b + 3]);
        f2 t3r = f2fma(xr[b + 3], NEG, xr[b + 1]), t3i = f2fma(xi[b + 3], NEG, xi[b + 1]);

        xr[b]     = f2add(t0r, t2r);              xi[b]     = f2add(t0i, t2i);
        xr[b + 1] = f2add(t1r, t3i);              xi[b + 1] = f2fma(t3r, NEG, t1i);
        xr[b + 2] = f2fma(t2r, NEG, t0r);         xi[b + 2] = f2fma(t2i, NEG, t0i);
        xr[b + 3] = f2fma(t3i, NEG, t1r);         xi[b + 3] = f2add(t1i, t3r);
    }
}

// Full 512-point packed FFT (two independent FFTs in f2 lanes).
// Output: slot p on lane (=16*par+k1) holds bin k = lane + 32*dig4(p).
// Single-round float4 slab transpose with the n3 radix-2 AND the w32^{n2}
// odd-branch twiddle both folded into the read (FSEL'd constants, no branch).
__device__ __forceinline__ void fft512D(f2 (&xr)[16], f2 (&xi)[16],
                                        int lane, int par,
                                        ulonglong2* __restrict__ slab,
                                        f2 NEG, f2 SP)
{
    constexpr float W32R_[16] = {
        1.f, 0.98078528f, 0.92387953f, 0.83146961f, 0.70710678f, 0.55557023f,
        0.38268343f, 0.19509032f, 0.f, -0.19509032f, -0.38268343f, -0.55557023f,
        -0.70710678f, -0.83146961f, -0.92387953f, -0.98078528f };
    constexpr float W32I_[16] = {
        0.f, -0.19509032f, -0.38268343f, -0.55557023f, -0.70710678f, -0.83146961f,
        -0.92387953f, -0.98078528f, -1.f, -0.98078528f, -0.92387953f, -0.83146961f,
        -0.70710678f, -0.55557023f, -0.38268343f, -0.19509032f };

    // pass 1: FFT16 over slots (n1)
    fft16_r4(xr, xi, NEG);

    // four-step twiddle: slot p *= w512^{lane * dig4(p)} (global table, L1-resident)
    #pragma unroll
    for (int p = 1; p < 16; ++p) {
        float2 w = __ldg(&g_tw512[p * 32 + lane]);
        f2 wr = f2splat(w.x), wi = f2splat(w.y);
        f2 t1 = f2mul(xi[p], wi);
        f2 ni = f2fma(xi[p], wr, f2mul(xr[p], wi));
        xr[p] = f2fma(t1, NEG, f2mul(xr[p], wr));
        xi[p] = ni;
    }

    const int wb = (lane & 15) * 33;    // read row base (pad-33 float4 rows)

    // single-round transpose: {xr,xi} as one 16B element; fold n3 radix-2 and
    // odd-branch w32^{n2} twiddle into the read:
    //   par=0: x = y0 + y1
    //   par=1: x = (y0 - y1) * w32^{s}
    __syncwarp();
    #pragma unroll
    for (int p = 0; p < 16; ++p)
        slab[dig4c(p) * 33 + lane] = make_ulonglong2(xr[p], xi[p]);
    __syncwarp();
    #pragma unroll
    for (int s = 0; s < 16; ++s) {
        ulonglong2 y0 = slab[wb + s];
        ulonglong2 y1 = slab[wb + s + 16];
        f2 dr = f2fma((f2)y1.x, SP, (f2)y0.x);   // y0r +/- y1r
        f2 di = f2fma((f2)y1.y, SP, (f2)y0.y);
        if (s == 0) {
            xr[0] = dr; xi[0] = di;
        } else {
            float cr  = par ? W32R_[s] : 1.f;    // FSEL (alu pipe)
            float ci  = par ? W32I_[s] : 0.f;
            float cin = par ? -W32I_[s] : 0.f;
            f2 wr = f2splat(cr), wi = f2splat(ci), win = f2splat(cin);
            xr[s] = f2fma(di, win, f2mul(dr, wr));
            xi[s] = f2fma(di, wr,  f2mul(dr, wi));
        }
    }

    // pass 2: FFT16 over n2 -> k2 = 2*dig4(slot) + par
    fft16_r4(xr, xi, NEG);
}

// out[b] = Im( sum_f Z[f]^2 * conj(T[f]) ) / (2*D), Z = FFT(h+ir), T = FFT(t).
// Packed per row: lo = Z-FFT, hi = T-FFT. Independent rows -> full pipelining.
// Geometry: 96-thread blocks x 6 blocks/SM = 18 warps/SM at <=113 regs.
__global__ void __launch_bounds__(96, 6)
hole_kernel(const float* __restrict__ h, const float* __restrict__ r,
            const float* __restrict__ t, float* __restrict__ out, int nrows)
{
    const int lane = threadIdx.x & 31;
    const int wid  = threadIdx.x >> 5;
    const int warp = blockIdx.x * 3 + wid;
    const int nw   = gridDim.x * 3;
    const int par  = lane >> 4;

    __shared__ ulonglong2 slab_s[3][16 * 33];   // 8.25 KB/warp float4 slab
    ulonglong2* __restrict__ slab = slab_s[wid];

    const f2 NEG = f2splat(-1.f);
    const f2 SP  = f2splat(par ? -1.f : 1.f);

    for (int row = warp; row < nrows; row += nw) {
        size_t base = (size_t)row * 512 + (size_t)lane;
        const float* hp = h + base;
        const float* rp = r + base;
        const float* tp = t + base;

        // coalesced loads; lo = Z input (h + i r), hi = T input (t + i 0)
        f2 xr[16], xi[16];
        #pragma unroll
        for (int s = 0; s < 16; ++s) {
            float hv = hp[32 * s];
            float tv = tp[32 * s];
            float rv = rp[32 * s];
            xr[s] = f2pack(hv, tv);
            xi[s] = f2pack(rv, 0.f);
        }

        // prefetch next row's 48 x 128B lines to L2:
        //   instr 1: lanes 0-15 cover h lines, lanes 16-31 cover r lines
        //   instr 2: lanes 0-15 cover t lines (upper lanes predicated off)
        {
            int nrow = row + nw;
            if (nrow < nrows) {
                size_t nb = (size_t)nrow * 512 + (size_t)((lane & 15) * 32);
                const float* p0 = par ? (r + nb) : (h + nb);
                asm volatile("prefetch.global.L2 [%0];" :: "l"(p0));
                if (!par) {
                    const float* p1 = t + nb;
                    asm volatile("prefetch.global.L2 [%0];" :: "l"(p1));
                }
            }
        }

        fft512D(xr, xi, lane, par, slab, NEG, SP);

        // reduction: out = 2*sum(ab*tr) - sum((a^2-b^2)*ti), factor 2 hoisted.
        float accA0 = 0.f, accA1 = 0.f, accB0 = 0.f, accB1 = 0.f;
        #pragma unroll
        for (int s = 0; s < 16; ++s) {
            float a, tr, b, ti;
            f2unpack(xr[s], a, tr);    // lo = Re Z, hi = Re T
            f2unpack(xi[s], b, ti);    // lo = Im Z, hi = Im T
            float ab  = a * b;
            float b2  = b * b;
            float re2 = fmaf(a, a, -b2);           // a^2 - b^2
            if (s & 1) { accA1 = fmaf(ab, tr, accA1); accB1 = fmaf(re2, ti, accB1); }
            else       { accA0 = fmaf(ab, tr, accA0); accB0 = fmaf(re2, ti, accB0); }
        }
        float acc = fmaf(2.f, accA0 + accA1, -(accB0 + accB1));

        #pragma unroll
        for (int o = 16; o; o >>= 1)
            acc += __shfl_xor_sync(FULL_MASK, acc, o);

        if (lane == 0) out[row] = acc * (1.f / 1024.f);   // 1/(2*D)
    }
}

extern "C" void kernel_launch(void* const* d_in, const int* in_sizes, int n_in,
                              void* d_out, int out_size)
{
    const float* h = (const float*)d_in[0];
    const float* r = (const float*)d_in[1];
    const float* t = (const float*)d_in[2];
    float* out = (float*)d_out;

    int nrows = in_sizes[0] / 512;      // 131072

    init_tw_kernel<<<1, 512>>>();       // idempotent, graph-capturable
    hole_kernel<<<5462, 96>>>(h, r, t, out, nrows);   // ~16386 warps -> 8 rows/warp
}